// round 2
// baseline (speedup 1.0000x reference)
#include <cuda_runtime.h>
#include <cstdint>

#define BATCH  1024
#define TSTEPS 80
#define EDIM   100
#define UDIM   256
#define VOCAB  10000
#define NCOL   1024   // 4 gates * U, packed col = u*4 + g  (g: 0=f,1=i,2=c,3=o)
#define HSTR   512    // hcat row stride: [h2(256) | h1(256)]
#define NBLK   148

// ---------------- device scratch (static: no allocations) ----------------
__device__ float    g_proj[(size_t)VOCAB * NCOL];   // 41 MB: emb @ Wx + b1, gate-interleaved
__device__ float    g_W1p[UDIM * NCOL];             // layer1 recurrent weights, [k][u*4+g]
__device__ float    g_W2p[2 * UDIM * NCOL];         // layer2 weights, [k][u*4+g], k<256 -> h2, k>=256 -> h1
__device__ float    g_b2p[NCOL];
__device__ float    g_hcat[2][BATCH * HSTR];        // ping-pong h state
__device__ unsigned g_cnt;

// ---------------- math helpers ----------------
__device__ __forceinline__ float sigf(float x) { return 1.0f / (1.0f + __expf(-x)); }
__device__ __forceinline__ float tanh_(float x) {
    x = fminf(fmaxf(x, -20.0f), 20.0f);
    float e = __expf(-2.0f * x);
    return (1.0f - e) / (1.0f + e);
}

// grid barrier: monotonic counter, all NBLK blocks resident
__device__ __forceinline__ void gsync(unsigned &target)
{
    __syncthreads();
    if (threadIdx.x == 0) {
        __threadfence();
        atomicAdd(&g_cnt, 1u);
        target += NBLK;
        while (*((volatile unsigned *)&g_cnt) < target) { __nanosleep(32); }
        __threadfence();
    }
    __syncthreads();
}

// ---------------- init: zero state, pack weights ----------------
__global__ void init_kernel(
    const float *wf1, const float *wi1, const float *wc1, const float *wo1,
    const float *wf2, const float *wi2, const float *wc2, const float *wo2,
    const float *bf2, const float *bi2, const float *bc2, const float *bo2)
{
    long i = (long)blockIdx.x * blockDim.x + threadIdx.x;
    long stride = (long)gridDim.x * blockDim.x;
    for (long j = i; j < 2L * BATCH * HSTR; j += stride) ((float *)g_hcat)[j] = 0.0f;
    for (long j = i; j < (long)UDIM * NCOL; j += stride) {
        int k = (int)(j >> 10), col = (int)(j & 1023);
        int g = col & 3, u = col >> 2;
        const float *w = (g == 0) ? wf1 : (g == 1) ? wi1 : (g == 2) ? wc1 : wo1;
        g_W1p[j] = w[k * UDIM + u];
    }
    for (long j = i; j < 2L * UDIM * NCOL; j += stride) {
        int k = (int)(j >> 10), col = (int)(j & 1023);
        int g = col & 3, u = col >> 2;
        const float *w = (g == 0) ? wf2 : (g == 1) ? wi2 : (g == 2) ? wc2 : wo2;
        g_W2p[j] = w[k * UDIM + u];
    }
    for (long j = i; j < NCOL; j += stride) {
        int g = (int)(j & 3), u = (int)(j >> 2);
        const float *b = (g == 0) ? bf2 : (g == 1) ? bi2 : (g == 2) ? bc2 : bo2;
        g_b2p[j] = b[u];
    }
    if (i == 0) g_cnt = 0u;
}

// ---------------- proj: proj[v][u*4+g] = sum_k emb[v][k]*W{g}1[256+k][u] + b{g}1[u] ----------------
// tiled GEMM M=10000 N=1024 K=100, BM=64 BN=128 BK=16 (7 k-tiles, zero-padded)
__global__ __launch_bounds__(256) void proj_kernel(
    const float *__restrict__ emb,
    const float *__restrict__ wf1, const float *__restrict__ wi1,
    const float *__restrict__ wc1, const float *__restrict__ wo1,
    const float *__restrict__ bf1, const float *__restrict__ bi1,
    const float *__restrict__ bc1, const float *__restrict__ bo1)
{
    __shared__ float As[16][68];
    __shared__ float Bs[16][128];
    const int tid = threadIdx.x;
    const int tx = tid & 15, ty = tid >> 4;
    const int bid = blockIdx.x;
    const int mT = bid >> 3, nT = bid & 7;
    const int m0 = mT << 6, n0 = nT << 7;
    const int la_m = tid >> 2, la_k = (tid & 3) << 2;
    const int lb_k = tid >> 4, lb_n = (tid & 15) << 3;

    float acc[4][8];
#pragma unroll
    for (int r = 0; r < 4; ++r)
#pragma unroll
        for (int j = 0; j < 8; ++j) acc[r][j] = 0.0f;

#pragma unroll 1
    for (int kt = 0; kt < 7; ++kt) {
        const int k0 = kt << 4;
        // load A fragment (emb), guarded
        float4 pa = make_float4(0.f, 0.f, 0.f, 0.f);
        {
            int v = m0 + la_m, k = k0 + la_k;
            if (v < VOCAB && k < EDIM)
                pa = *(const float4 *)(emb + (size_t)v * EDIM + k);
        }
        // gather B fragment from the 4 gate weight matrices (x-rows), guarded
        float pb[8];
        {
            int k = k0 + lb_k;
            bool val = (k < EDIM);
            int wrow = (UDIM + k) * UDIM;
            int uc = (n0 + lb_n) >> 2;
            pb[0] = val ? __ldg(&wf1[wrow + uc]) : 0.f;
            pb[1] = val ? __ldg(&wi1[wrow + uc]) : 0.f;
            pb[2] = val ? __ldg(&wc1[wrow + uc]) : 0.f;
            pb[3] = val ? __ldg(&wo1[wrow + uc]) : 0.f;
            pb[4] = val ? __ldg(&wf1[wrow + uc + 1]) : 0.f;
            pb[5] = val ? __ldg(&wi1[wrow + uc + 1]) : 0.f;
            pb[6] = val ? __ldg(&wc1[wrow + uc + 1]) : 0.f;
            pb[7] = val ? __ldg(&wo1[wrow + uc + 1]) : 0.f;
        }
        __syncthreads();
        As[la_k + 0][la_m] = pa.x;
        As[la_k + 1][la_m] = pa.y;
        As[la_k + 2][la_m] = pa.z;
        As[la_k + 3][la_m] = pa.w;
#pragma unroll
        for (int j = 0; j < 8; ++j) Bs[lb_k][lb_n + j] = pb[j];
        __syncthreads();
#pragma unroll
        for (int kk = 0; kk < 16; ++kk) {
            float4 a4 = *(const float4 *)&As[kk][ty << 2];
            float4 b4a = *(const float4 *)&Bs[kk][tx << 3];
            float4 b4b = *(const float4 *)&Bs[kk][(tx << 3) + 4];
            float av[4] = {a4.x, a4.y, a4.z, a4.w};
            float bv[8] = {b4a.x, b4a.y, b4a.z, b4a.w, b4b.x, b4b.y, b4b.z, b4b.w};
#pragma unroll
            for (int r = 0; r < 4; ++r)
#pragma unroll
                for (int j = 0; j < 8; ++j) acc[r][j] = fmaf(av[r], bv[j], acc[r][j]);
        }
    }
    // epilogue: add biases, store
#pragma unroll
    for (int r = 0; r < 4; ++r) {
        int v = m0 + (ty << 2) + r;
        if (v < VOCAB) {
            int colb = n0 + (tx << 3);
            int u = colb >> 2;
            float *dst = g_proj + (size_t)v * NCOL + colb;
            dst[0] = acc[r][0] + __ldg(&bf1[u]);
            dst[1] = acc[r][1] + __ldg(&bi1[u]);
            dst[2] = acc[r][2] + __ldg(&bc1[u]);
            dst[3] = acc[r][3] + __ldg(&bo1[u]);
            dst[4] = acc[r][4] + __ldg(&bf1[u + 1]);
            dst[5] = acc[r][5] + __ldg(&bi1[u + 1]);
            dst[6] = acc[r][6] + __ldg(&bc1[u + 1]);
            dst[7] = acc[r][7] + __ldg(&bo1[u + 1]);
        }
    }
}

// ---------------- recurrent GEMM tile: BM=64 BN=128 BK=16, double-buffered ----------------
// A element (b,k) = ((k < ksplit) ? A0 : A1)[b*HSTR + k]   (loaded via L2 - cross-SM coherent)
template <int KT>
__device__ __forceinline__ void gemm_tile(
    const float *A0, const float *A1, int ksplit,
    const float *__restrict__ W,
    float (&acc)[4][8], int m0, int n0,
    float (*As)[16][68], float (*Bs)[16][128])
{
    const int tid = threadIdx.x;
    const int la_m = tid >> 2, la_k = (tid & 3) << 2;
    const int lb_k = tid >> 4, lb_n = (tid & 15) << 3;
    const int tx = tid & 15, ty = tid >> 4;

    float4 pa, pb0, pb1;
    {
        const float *Ab = (0 < ksplit) ? A0 : A1;
        pa = __ldcg((const float4 *)(Ab + (size_t)(m0 + la_m) * HSTR + la_k));
        const float *wp = W + (size_t)lb_k * NCOL + n0 + lb_n;
        pb0 = *(const float4 *)wp;
        pb1 = *(const float4 *)(wp + 4);
    }
    As[0][la_k + 0][la_m] = pa.x;
    As[0][la_k + 1][la_m] = pa.y;
    As[0][la_k + 2][la_m] = pa.z;
    As[0][la_k + 3][la_m] = pa.w;
    *(float4 *)&Bs[0][lb_k][lb_n] = pb0;
    *(float4 *)&Bs[0][lb_k][lb_n + 4] = pb1;
    __syncthreads();
    int cur = 0;
#pragma unroll 1
    for (int kt = 0; kt < KT; ++kt) {
        const bool more = (kt + 1 < KT);
        if (more) {
            const int k0 = (kt + 1) << 4;
            const float *Ab = (k0 < ksplit) ? A0 : A1;
            pa = __ldcg((const float4 *)(Ab + (size_t)(m0 + la_m) * HSTR + k0 + la_k));
            const float *wp = W + (size_t)(k0 + lb_k) * NCOL + n0 + lb_n;
            pb0 = *(const float4 *)wp;
            pb1 = *(const float4 *)(wp + 4);
        }
#pragma unroll
        for (int kk = 0; kk < 16; ++kk) {
            float4 a4 = *(const float4 *)&As[cur][kk][ty << 2];
            float4 b4a = *(const float4 *)&Bs[cur][kk][tx << 3];
            float4 b4b = *(const float4 *)&Bs[cur][kk][(tx << 3) + 4];
            float av[4] = {a4.x, a4.y, a4.z, a4.w};
            float bv[8] = {b4a.x, b4a.y, b4a.z, b4a.w, b4b.x, b4b.y, b4b.z, b4b.w};
#pragma unroll
            for (int r = 0; r < 4; ++r)
#pragma unroll
                for (int j = 0; j < 8; ++j) acc[r][j] = fmaf(av[r], bv[j], acc[r][j]);
        }
        if (more) {
            const int nb = cur ^ 1;
            As[nb][la_k + 0][la_m] = pa.x;
            As[nb][la_k + 1][la_m] = pa.y;
            As[nb][la_k + 2][la_m] = pa.z;
            As[nb][la_k + 3][la_m] = pa.w;
            *(float4 *)&Bs[nb][lb_k][lb_n] = pb0;
            *(float4 *)&Bs[nb][lb_k][lb_n + 4] = pb1;
        }
        __syncthreads();
        cur ^= 1;
    }
}

// ---------------- persistent recurrent kernel: 80 steps, grid barriers ----------------
__global__ __launch_bounds__(256, 1) void lstm_kernel(
    const int *__restrict__ tokens,
    const float *__restrict__ w_out,
    const float *__restrict__ b_out,
    float *__restrict__ out)
{
    __shared__ float As[2][16][68];
    __shared__ float Bs[2][16][128];
    const int tid = threadIdx.x;
    const int tx = tid & 15, ty = tid >> 4;
    const int bid = blockIdx.x;
    const bool worker = (bid < 128);
    const int mT = bid >> 3, nT = bid & 7;
    const int m0 = mT << 6, n0 = nT << 7;
    const int u0 = (n0 + (tx << 3)) >> 2;

    float c1s[4][2], c2s[4][2];
#pragma unroll
    for (int r = 0; r < 4; ++r) { c1s[r][0] = c1s[r][1] = 0.f; c2s[r][0] = c2s[r][1] = 0.f; }
    unsigned target = 0;

    for (int t = 0; t < TSTEPS; ++t) {
        const float *hA = g_hcat[t & 1];
        float *hB = g_hcat[(t + 1) & 1];

        // ---- phase A: layer-1 GEMM (K=256 over h1_old) + cell update ----
        if (worker) {
            float acc[4][8];
#pragma unroll
            for (int r = 0; r < 4; ++r)
#pragma unroll
                for (int j = 0; j < 8; ++j) acc[r][j] = 0.f;
            gemm_tile<16>(hA, hA + UDIM, 0, g_W1p, acc, m0, n0, As, Bs);
#pragma unroll
            for (int r = 0; r < 4; ++r) {
                int b = m0 + (ty << 2) + r;
                int tok = __ldg(&tokens[b * TSTEPS + t]);
                const float *pr = g_proj + (size_t)tok * NCOL + n0 + (tx << 3);
#pragma unroll
                for (int up = 0; up < 2; ++up) {
                    float pf = acc[r][up * 4 + 0] + __ldg(pr + up * 4 + 0);
                    float pi = acc[r][up * 4 + 1] + __ldg(pr + up * 4 + 1);
                    float pc = acc[r][up * 4 + 2] + __ldg(pr + up * 4 + 2);
                    float po = acc[r][up * 4 + 3] + __ldg(pr + up * 4 + 3);
                    float cn = sigf(pf) * c1s[r][up] + sigf(pi) * tanh_(pc);
                    c1s[r][up] = cn;
                    __stcg(&hB[(size_t)b * HSTR + UDIM + u0 + up], sigf(po) * tanh_(cn));
                }
            }
        }
        gsync(target);

        // ---- phase B: layer-2 GEMM (K=512 over [h2_old | h1_new]) + cell update ----
        if (worker) {
            float acc[4][8];
#pragma unroll
            for (int r = 0; r < 4; ++r)
#pragma unroll
                for (int j = 0; j < 8; ++j) acc[r][j] = 0.f;
            gemm_tile<32>(hA, hB, UDIM, g_W2p, acc, m0, n0, As, Bs);
#pragma unroll
            for (int r = 0; r < 4; ++r) {
                int b = m0 + (ty << 2) + r;
                const float *bb = g_b2p + n0 + (tx << 3);
#pragma unroll
                for (int up = 0; up < 2; ++up) {
                    float pf = acc[r][up * 4 + 0] + __ldg(bb + up * 4 + 0);
                    float pi = acc[r][up * 4 + 1] + __ldg(bb + up * 4 + 1);
                    float pc = acc[r][up * 4 + 2] + __ldg(bb + up * 4 + 2);
                    float po = acc[r][up * 4 + 3] + __ldg(bb + up * 4 + 3);
                    float cn = sigf(pf) * c2s[r][up] + sigf(pi) * tanh_(pc);
                    c2s[r][up] = cn;
                    __stcg(&hB[(size_t)b * HSTR + u0 + up], sigf(po) * tanh_(cn));
                }
            }
        }
        gsync(target);
    }

    // ---- final: out[b] = sigmoid(h2[b] . w_out + b_out); h2 in buffer (TSTEPS & 1) == 0 ----
    const float *h2 = g_hcat[0];
    int w = (bid << 3) + (tid >> 5);
    int lane = tid & 31;
    if (w < BATCH) {
        float s = 0.0f;
#pragma unroll
        for (int k = lane; k < UDIM; k += 32)
            s += __ldcg(&h2[(size_t)w * HSTR + k]) * __ldg(&w_out[k]);
#pragma unroll
        for (int off = 16; off > 0; off >>= 1)
            s += __shfl_down_sync(0xffffffffu, s, off);
        if (lane == 0) out[w] = sigf(s + __ldg(&b_out[0]));
    }
}

// ---------------- launch ----------------
extern "C" void kernel_launch(void *const *d_in, const int *in_sizes, int n_in,
                              void *d_out, int out_size)
{
    const int   *tokens = (const int *)d_in[0];
    const float *emb   = (const float *)d_in[1];
    const float *wf1 = (const float *)d_in[2];
    const float *bf1 = (const float *)d_in[3];
    const float *wi1 = (const float *)d_in[4];
    const float *bi1 = (const float *)d_in[5];
    const float *wc1 = (const float *)d_in[6];
    const float *bc1 = (const float *)d_in[7];
    const float *wo1 = (const float *)d_in[8];
    const float *bo1 = (const float *)d_in[9];
    const float *wf2 = (const float *)d_in[10];
    const float *bf2 = (const float *)d_in[11];
    const float *wi2 = (const float *)d_in[12];
    const float *bi2 = (const float *)d_in[13];
    const float *wc2 = (const float *)d_in[14];
    const float *bc2 = (const float *)d_in[15];
    const float *wo2 = (const float *)d_in[16];
    const float *bo2 = (const float *)d_in[17];
    const float *w_out = (const float *)d_in[18];
    const float *b_out = (const float *)d_in[19];
    float *out = (float *)d_out;

    init_kernel<<<1024, 256>>>(wf1, wi1, wc1, wo1, wf2, wi2, wc2, wo2, bf2, bi2, bc2, bo2);
    proj_kernel<<<1256, 256>>>(emb, wf1, wi1, wc1, wo1, bf1, bi1, bc1, bo1);
    lstm_kernel<<<NBLK, 256>>>(tokens, w_out, b_out, out);
}

// round 3
// speedup vs baseline: 1.0035x; 1.0035x over previous
#include <cuda_runtime.h>
#include <cstdint>

#define BATCH  1024
#define TSTEPS 80
#define EDIM   100
#define UDIM   256
#define VOCAB  10000
#define NCOL   1024   // 4 gates * U, packed col = u*4 + g  (g: 0=f,1=i,2=c,3=o)
#define HSTR   512    // hcat row stride: [h2(256) | h1(256)]
#define NBLK   148

typedef unsigned long long ull;

// ---------------- device scratch (static: no allocations) ----------------
__device__ float    g_proj[(size_t)VOCAB * NCOL];   // 41 MB: emb @ Wx + b1, gate-interleaved
__device__ float    g_W1p[UDIM * NCOL];             // layer1 recurrent weights, [k][u*4+g]
__device__ float    g_W2p[2 * UDIM * NCOL];         // layer2 weights, [k][u*4+g]
__device__ float    g_b2p[NCOL];
__device__ float    g_hcat[2][BATCH * HSTR];        // ping-pong h state
__device__ unsigned g_cnt;

// ---------------- packed fp32x2 helpers ----------------
__device__ __forceinline__ ull pack2(float lo, float hi) {
    ull r; asm("mov.b64 %0, {%1, %2};" : "=l"(r) : "f"(lo), "f"(hi)); return r;
}
__device__ __forceinline__ float2 unpack2(ull v) {
    float2 f; asm("mov.b64 {%0, %1}, %2;" : "=f"(f.x), "=f"(f.y) : "l"(v)); return f;
}
__device__ __forceinline__ void fma2(ull &d, ull a, ull b) {
    asm("fma.rn.f32x2 %0, %1, %2, %0;" : "+l"(d) : "l"(a), "l"(b));
}

// ---------------- math helpers ----------------
__device__ __forceinline__ float sigf(float x) { return 1.0f / (1.0f + __expf(-x)); }
__device__ __forceinline__ float tanh_(float x) {
    x = fminf(fmaxf(x, -20.0f), 20.0f);
    float e = __expf(-2.0f * x);
    return (1.0f - e) / (1.0f + e);
}

// grid barrier: monotonic counter, all NBLK blocks resident
__device__ __forceinline__ void gsync(unsigned &target)
{
    __syncthreads();
    if (threadIdx.x == 0) {
        __threadfence();
        atomicAdd(&g_cnt, 1u);
        target += NBLK;
        while (*((volatile unsigned *)&g_cnt) < target) { __nanosleep(32); }
        __threadfence();
    }
    __syncthreads();
}

// ---------------- init: zero state, pack weights ----------------
__global__ void init_kernel(
    const float *wf1, const float *wi1, const float *wc1, const float *wo1,
    const float *wf2, const float *wi2, const float *wc2, const float *wo2,
    const float *bf2, const float *bi2, const float *bc2, const float *bo2)
{
    long i = (long)blockIdx.x * blockDim.x + threadIdx.x;
    long stride = (long)gridDim.x * blockDim.x;
    for (long j = i; j < 2L * BATCH * HSTR; j += stride) ((float *)g_hcat)[j] = 0.0f;
    for (long j = i; j < (long)UDIM * NCOL; j += stride) {
        int k = (int)(j >> 10), col = (int)(j & 1023);
        int g = col & 3, u = col >> 2;
        const float *w = (g == 0) ? wf1 : (g == 1) ? wi1 : (g == 2) ? wc1 : wo1;
        g_W1p[j] = w[k * UDIM + u];
    }
    for (long j = i; j < 2L * UDIM * NCOL; j += stride) {
        int k = (int)(j >> 10), col = (int)(j & 1023);
        int g = col & 3, u = col >> 2;
        const float *w = (g == 0) ? wf2 : (g == 1) ? wi2 : (g == 2) ? wc2 : wo2;
        g_W2p[j] = w[k * UDIM + u];
    }
    for (long j = i; j < NCOL; j += stride) {
        int g = (int)(j & 3), u = (int)(j >> 2);
        const float *b = (g == 0) ? bf2 : (g == 1) ? bi2 : (g == 2) ? bc2 : bo2;
        g_b2p[j] = b[u];
    }
    if (i == 0) g_cnt = 0u;
}

// packed-pair microtile update: 16 fma.rn.f32x2 (+4 mov.b64) per kk
__device__ __forceinline__ void micro_fma2(
    ull (&acc)[4][4], const float *Asrow, const float *Bsrow, int tx, int ty)
{
    float4 a4 = *(const float4 *)(Asrow + (ty << 2));
    const ull *bp = (const ull *)(Bsrow + (tx << 3));
    ull b0 = bp[0], b1 = bp[1], b2 = bp[2], b3 = bp[3];
    ull av;
    av = pack2(a4.x, a4.x);
    fma2(acc[0][0], av, b0); fma2(acc[0][1], av, b1);
    fma2(acc[0][2], av, b2); fma2(acc[0][3], av, b3);
    av = pack2(a4.y, a4.y);
    fma2(acc[1][0], av, b0); fma2(acc[1][1], av, b1);
    fma2(acc[1][2], av, b2); fma2(acc[1][3], av, b3);
    av = pack2(a4.z, a4.z);
    fma2(acc[2][0], av, b0); fma2(acc[2][1], av, b1);
    fma2(acc[2][2], av, b2); fma2(acc[2][3], av, b3);
    av = pack2(a4.w, a4.w);
    fma2(acc[3][0], av, b0); fma2(acc[3][1], av, b1);
    fma2(acc[3][2], av, b2); fma2(acc[3][3], av, b3);
}

// ---------------- proj: proj[v][u*4+g] = sum_k emb[v][k]*W{g}1[256+k][u] + b{g}1[u] ----------------
__global__ __launch_bounds__(256) void proj_kernel(
    const float *__restrict__ emb,
    const float *__restrict__ wf1, const float *__restrict__ wi1,
    const float *__restrict__ wc1, const float *__restrict__ wo1,
    const float *__restrict__ bf1, const float *__restrict__ bi1,
    const float *__restrict__ bc1, const float *__restrict__ bo1)
{
    __shared__ float As[16][68];
    __shared__ float Bs[16][128];
    const int tid = threadIdx.x;
    const int tx = tid & 15, ty = tid >> 4;
    const int bid = blockIdx.x;
    const int mT = bid >> 3, nT = bid & 7;
    const int m0 = mT << 6, n0 = nT << 7;
    const int la_m = tid >> 2, la_k = (tid & 3) << 2;
    const int lb_k = tid >> 4, lb_n = (tid & 15) << 3;

    ull acc[4][4];
#pragma unroll
    for (int r = 0; r < 4; ++r)
#pragma unroll
        for (int j = 0; j < 4; ++j) acc[r][j] = 0ull;

#pragma unroll 1
    for (int kt = 0; kt < 7; ++kt) {
        const int k0 = kt << 4;
        float4 pa = make_float4(0.f, 0.f, 0.f, 0.f);
        {
            int v = m0 + la_m, k = k0 + la_k;
            if (v < VOCAB && k < EDIM)
                pa = *(const float4 *)(emb + (size_t)v * EDIM + k);
        }
        float pb[8];
        {
            int k = k0 + lb_k;
            bool val = (k < EDIM);
            int wrow = (UDIM + k) * UDIM;
            int uc = (n0 + lb_n) >> 2;
            pb[0] = val ? __ldg(&wf1[wrow + uc]) : 0.f;
            pb[1] = val ? __ldg(&wi1[wrow + uc]) : 0.f;
            pb[2] = val ? __ldg(&wc1[wrow + uc]) : 0.f;
            pb[3] = val ? __ldg(&wo1[wrow + uc]) : 0.f;
            pb[4] = val ? __ldg(&wf1[wrow + uc + 1]) : 0.f;
            pb[5] = val ? __ldg(&wi1[wrow + uc + 1]) : 0.f;
            pb[6] = val ? __ldg(&wc1[wrow + uc + 1]) : 0.f;
            pb[7] = val ? __ldg(&wo1[wrow + uc + 1]) : 0.f;
        }
        __syncthreads();
        As[la_k + 0][la_m] = pa.x;
        As[la_k + 1][la_m] = pa.y;
        As[la_k + 2][la_m] = pa.z;
        As[la_k + 3][la_m] = pa.w;
#pragma unroll
        for (int j = 0; j < 8; ++j) Bs[lb_k][lb_n + j] = pb[j];
        __syncthreads();
#pragma unroll
        for (int kk = 0; kk < 16; ++kk)
            micro_fma2(acc, As[kk], Bs[kk], tx, ty);
    }
#pragma unroll
    for (int r = 0; r < 4; ++r) {
        int v = m0 + (ty << 2) + r;
        if (v < VOCAB) {
            int colb = n0 + (tx << 3);
            int u = colb >> 2;
            float *dst = g_proj + (size_t)v * NCOL + colb;
            float2 v0 = unpack2(acc[r][0]), v1 = unpack2(acc[r][1]);
            float2 v2 = unpack2(acc[r][2]), v3 = unpack2(acc[r][3]);
            dst[0] = v0.x + __ldg(&bf1[u]);
            dst[1] = v0.y + __ldg(&bi1[u]);
            dst[2] = v1.x + __ldg(&bc1[u]);
            dst[3] = v1.y + __ldg(&bo1[u]);
            dst[4] = v2.x + __ldg(&bf1[u + 1]);
            dst[5] = v2.y + __ldg(&bi1[u + 1]);
            dst[6] = v3.x + __ldg(&bc1[u + 1]);
            dst[7] = v3.y + __ldg(&bo1[u + 1]);
        }
    }
}

// ---------------- recurrent GEMM tile: BM=64 BN=128 BK=16, double-buffered ----------------
template <int KT>
__device__ __forceinline__ void gemm_tile(
    const float *A0, const float *A1, int ksplit,
    const float *__restrict__ W,
    ull (&acc)[4][4], int m0, int n0,
    float (*As)[16][68], float (*Bs)[16][128])
{
    const int tid = threadIdx.x;
    const int la_m = tid >> 2, la_k = (tid & 3) << 2;
    const int lb_k = tid >> 4, lb_n = (tid & 15) << 3;
    const int tx = tid & 15, ty = tid >> 4;

    float4 pa, pb0, pb1;
    {
        const float *Ab = (0 < ksplit) ? A0 : A1;
        pa = __ldcg((const float4 *)(Ab + (size_t)(m0 + la_m) * HSTR + la_k));
        const float *wp = W + (size_t)lb_k * NCOL + n0 + lb_n;
        pb0 = *(const float4 *)wp;
        pb1 = *(const float4 *)(wp + 4);
    }
    As[0][la_k + 0][la_m] = pa.x;
    As[0][la_k + 1][la_m] = pa.y;
    As[0][la_k + 2][la_m] = pa.z;
    As[0][la_k + 3][la_m] = pa.w;
    *(float4 *)&Bs[0][lb_k][lb_n] = pb0;
    *(float4 *)&Bs[0][lb_k][lb_n + 4] = pb1;
    __syncthreads();
    int cur = 0;
#pragma unroll 1
    for (int kt = 0; kt < KT; ++kt) {
        const bool more = (kt + 1 < KT);
        if (more) {
            const int k0 = (kt + 1) << 4;
            const float *Ab = (k0 < ksplit) ? A0 : A1;
            pa = __ldcg((const float4 *)(Ab + (size_t)(m0 + la_m) * HSTR + k0 + la_k));
            const float *wp = W + (size_t)(k0 + lb_k) * NCOL + n0 + lb_n;
            pb0 = *(const float4 *)wp;
            pb1 = *(const float4 *)(wp + 4);
        }
#pragma unroll
        for (int kk = 0; kk < 16; ++kk)
            micro_fma2(acc, As[cur][kk], Bs[cur][kk], tx, ty);
        if (more) {
            const int nb = cur ^ 1;
            As[nb][la_k + 0][la_m] = pa.x;
            As[nb][la_k + 1][la_m] = pa.y;
            As[nb][la_k + 2][la_m] = pa.z;
            As[nb][la_k + 3][la_m] = pa.w;
            *(float4 *)&Bs[nb][lb_k][lb_n] = pb0;
            *(float4 *)&Bs[nb][lb_k][lb_n + 4] = pb1;
        }
        __syncthreads();
        cur ^= 1;
    }
}

// ---------------- persistent recurrent kernel: 80 steps, grid barriers ----------------
__global__ __launch_bounds__(256, 1) void lstm_kernel(
    const int *__restrict__ tokens,
    const float *__restrict__ w_out,
    const float *__restrict__ b_out,
    float *__restrict__ out)
{
    __shared__ float As[2][16][68];
    __shared__ float Bs[2][16][128];
    const int tid = threadIdx.x;
    const int tx = tid & 15, ty = tid >> 4;
    const int bid = blockIdx.x;
    const bool worker = (bid < 128);
    const int mT = bid >> 3, nT = bid & 7;
    const int m0 = mT << 6, n0 = nT << 7;
    const int u0 = (n0 + (tx << 3)) >> 2;

    float c1s[4][2], c2s[4][2];
#pragma unroll
    for (int r = 0; r < 4; ++r) { c1s[r][0] = c1s[r][1] = 0.f; c2s[r][0] = c2s[r][1] = 0.f; }
    unsigned target = 0;

    for (int t = 0; t < TSTEPS; ++t) {
        const float *hA = g_hcat[t & 1];
        float *hB = g_hcat[(t + 1) & 1];

        // ---- phase A: layer-1 GEMM (K=256 over h1_old) + cell update ----
        if (worker) {
            ull acc[4][4];
#pragma unroll
            for (int r = 0; r < 4; ++r)
#pragma unroll
                for (int j = 0; j < 4; ++j) acc[r][j] = 0ull;
            gemm_tile<16>(hA, hA + UDIM, 0, g_W1p, acc, m0, n0, As, Bs);
#pragma unroll
            for (int r = 0; r < 4; ++r) {
                int b = m0 + (ty << 2) + r;
                int tok = __ldg(&tokens[b * TSTEPS + t]);
                const float *pr = g_proj + (size_t)tok * NCOL + n0 + (tx << 3);
#pragma unroll
                for (int up = 0; up < 2; ++up) {
                    float2 vfi = unpack2(acc[r][up * 2 + 0]);
                    float2 vco = unpack2(acc[r][up * 2 + 1]);
                    float pf = vfi.x + __ldg(pr + up * 4 + 0);
                    float pi = vfi.y + __ldg(pr + up * 4 + 1);
                    float pc = vco.x + __ldg(pr + up * 4 + 2);
                    float po = vco.y + __ldg(pr + up * 4 + 3);
                    float cn = sigf(pf) * c1s[r][up] + sigf(pi) * tanh_(pc);
                    c1s[r][up] = cn;
                    __stcg(&hB[(size_t)b * HSTR + UDIM + u0 + up], sigf(po) * tanh_(cn));
                }
            }
        }
        gsync(target);

        // ---- phase B: layer-2 GEMM (K=512 over [h2_old | h1_new]) + cell update ----
        if (worker) {
            ull acc[4][4];
#pragma unroll
            for (int r = 0; r < 4; ++r)
#pragma unroll
                for (int j = 0; j < 4; ++j) acc[r][j] = 0ull;
            gemm_tile<32>(hA, hB, UDIM, g_W2p, acc, m0, n0, As, Bs);
#pragma unroll
            for (int r = 0; r < 4; ++r) {
                int b = m0 + (ty << 2) + r;
                const float *bb = g_b2p + n0 + (tx << 3);
#pragma unroll
                for (int up = 0; up < 2; ++up) {
                    float2 vfi = unpack2(acc[r][up * 2 + 0]);
                    float2 vco = unpack2(acc[r][up * 2 + 1]);
                    float pf = vfi.x + __ldg(bb + up * 4 + 0);
                    float pi = vfi.y + __ldg(bb + up * 4 + 1);
                    float pc = vco.x + __ldg(bb + up * 4 + 2);
                    float po = vco.y + __ldg(bb + up * 4 + 3);
                    float cn = sigf(pf) * c2s[r][up] + sigf(pi) * tanh_(pc);
                    c2s[r][up] = cn;
                    __stcg(&hB[(size_t)b * HSTR + u0 + up], sigf(po) * tanh_(cn));
                }
            }
        }
        gsync(target);
    }

    // ---- final: out[b] = sigmoid(h2[b] . w_out + b_out) ----
    const float *h2 = g_hcat[0];
    int w = (bid << 3) + (tid >> 5);
    int lane = tid & 31;
    if (w < BATCH) {
        float s = 0.0f;
#pragma unroll
        for (int k = lane; k < UDIM; k += 32)
            s += __ldcg(&h2[(size_t)w * HSTR + k]) * __ldg(&w_out[k]);
#pragma unroll
        for (int off = 16; off > 0; off >>= 1)
            s += __shfl_down_sync(0xffffffffu, s, off);
        if (lane == 0) out[w] = sigf(s + __ldg(&b_out[0]));
    }
}

// ---------------- launch ----------------
extern "C" void kernel_launch(void *const *d_in, const int *in_sizes, int n_in,
                              void *d_out, int out_size)
{
    const int   *tokens = (const int *)d_in[0];
    const float *emb   = (const float *)d_in[1];
    const float *wf1 = (const float *)d_in[2];
    const float *bf1 = (const float *)d_in[3];
    const float *wi1 = (const float *)d_in[4];
    const float *bi1 = (const float *)d_in[5];
    const float *wc1 = (const float *)d_in[6];
    const float *bc1 = (const float *)d_in[7];
    const float *wo1 = (const float *)d_in[8];
    const float *bo1 = (const float *)d_in[9];
    const float *wf2 = (const float *)d_in[10];
    const float *bf2 = (const float *)d_in[11];
    const float *wi2 = (const float *)d_in[12];
    const float *bi2 = (const float *)d_in[13];
    const float *wc2 = (const float *)d_in[14];
    const float *bc2 = (const float *)d_in[15];
    const float *wo2 = (const float *)d_in[16];
    const float *bo2 = (const float *)d_in[17];
    const float *w_out = (const float *)d_in[18];
    const float *b_out = (const float *)d_in[19];
    float *out = (float *)d_out;

    init_kernel<<<1024, 256>>>(wf1, wi1, wc1, wo1, wf2, wi2, wc2, wo2, bf2, bi2, bc2, bo2);
    proj_kernel<<<1256, 256>>>(emb, wf1, wi1, wc1, wo1, bf1, bi1, bc1, bo1);
    lstm_kernel<<<NBLK, 256>>>(tokens, w_out, b_out, out);
}

// round 5
// speedup vs baseline: 1.8730x; 1.8665x over previous
#include <cuda_runtime.h>
#include <cuda_bf16.h>
#include <cstdint>

#define BATCH  1024
#define TSTEPS 80
#define EDIM   100
#define UDIM   256
#define VOCAB  10000
#define NCOL   1024   // 4 gates * U, packed col = u*4+g (g:0=f,1=i,2=c,3=o)
#define NBLK   128

// ---- smem layout (bytes) ----
#define SM_A     0         // 2 buf x 2 pl x 128 rows x 48B = 24576
#define A_BUF    12288
#define A_PL     6144
#define A_PITCH  48
#define SM_W1    24576     // 2 pl x 64 n x 528B = 67584
#define W1_PL    33792
#define W1_PITCH 528
#define SM_W2    92160     // 2 pl x 64 n x 1040B = 133120
#define W2_PL    66560
#define W2_PITCH 1040
#define SMEM_TOTAL 225280

// per-nT packed weight slice in bf16 elems
#define WSLICE   100352    // = 2*64*264 (L1) + 2*64*520 (L2)
#define W1_PL_E  16896
#define W2_BASE_E 33792
#define W2_PL_E  33280

// ---------------- device scratch ----------------
__device__ float          g_proj[(size_t)VOCAB * NCOL];  // emb@Wx+b1, fp32, gate-interleaved
__device__ __nv_bfloat16  g_Wpk[16 * WSLICE];            // packed bf16 hi/lo weights per nT
__device__ float          g_b2p[NCOL];
__device__ __nv_bfloat16  g_hbf[2][2][BATCH][512];       // [buf][plane][b][col] col: 0-255 h2, 256-511 h1
__device__ float          g_h2f[BATCH][UDIM];
__device__ unsigned       g_cnt;

// ---------------- helpers ----------------
__device__ __forceinline__ uint32_t smem_u32(const void *p) {
    uint32_t a;
    asm("{ .reg .u64 t; cvta.to.shared.u64 t, %1; cvt.u32.u64 %0, t; }" : "=r"(a) : "l"(p));
    return a;
}
__device__ __forceinline__ void mma_bf16(float *c, const uint32_t *a, const uint32_t *b) {
    asm volatile(
        "mma.sync.aligned.m16n8k16.row.col.f32.bf16.bf16.f32 "
        "{%0,%1,%2,%3}, {%4,%5,%6,%7}, {%8,%9}, {%0,%1,%2,%3};"
        : "+f"(c[0]), "+f"(c[1]), "+f"(c[2]), "+f"(c[3])
        : "r"(a[0]), "r"(a[1]), "r"(a[2]), "r"(a[3]), "r"(b[0]), "r"(b[1]));
}
__device__ __forceinline__ void ldmatrix4(uint32_t *r, uint32_t addr) {
    asm volatile("ldmatrix.sync.aligned.m8n8.x4.shared.b16 {%0,%1,%2,%3}, [%4];"
                 : "=r"(r[0]), "=r"(r[1]), "=r"(r[2]), "=r"(r[3]) : "r"(addr));
}
__device__ __forceinline__ void cpa16(uint32_t dst, const void *src) {
    asm volatile("cp.async.cg.shared.global [%0], [%1], 16;" :: "r"(dst), "l"(src) : "memory");
}
__device__ __forceinline__ float sigf(float x) { return 1.0f / (1.0f + __expf(-x)); }
__device__ __forceinline__ float tanh_(float x) {
    x = fminf(fmaxf(x, -20.0f), 20.0f);
    float e = __expf(-2.0f * x);
    return (1.0f - e) / (1.0f + e);
}
__device__ __forceinline__ void gsync(unsigned &target) {
    __syncthreads();
    if (threadIdx.x == 0) {
        __threadfence();
        atomicAdd(&g_cnt, 1u);
        target += NBLK;
        while (*((volatile unsigned *)&g_cnt) < target) { __nanosleep(32); }
        __threadfence();
    }
    __syncthreads();
}

// ---------------- init: pack bf16 hi/lo weights, zero state ----------------
__global__ void init_kernel(
    const float *wf1, const float *wi1, const float *wc1, const float *wo1,
    const float *wf2, const float *wi2, const float *wc2, const float *wo2,
    const float *bf2, const float *bi2, const float *bc2, const float *bo2)
{
    long i = (long)blockIdx.x * blockDim.x + threadIdx.x;
    long stride = (long)gridDim.x * blockDim.x;
    // zero h state (2*2*1024*512 bf16 = 1M u32)
    for (long j = i; j < 1024L * 1024L; j += stride) ((uint32_t *)g_hbf)[j] = 0u;
    // pack W^T slices: per nT: [L1 pl0|pl1 (64x264)], [L2 pl0|pl1 (64x520)]
    for (long j = i; j < 16L * 64L * 768L; j += stride) {
        int nT = (int)(j / (64 * 768));
        int rem = (int)(j % (64 * 768));
        int n = rem / 768, k = rem % 768;
        int col = nT * 64 + n;
        int u = col >> 2, g = col & 3;
        float val;
        long off;
        if (k < 256) {
            const float *w = (g == 0) ? wf1 : (g == 1) ? wi1 : (g == 2) ? wc1 : wo1;
            val = w[k * UDIM + u];
            off = (long)nT * WSLICE + n * 264 + k;
            __nv_bfloat16 hi = __float2bfloat16(val);
            __nv_bfloat16 lo = __float2bfloat16(val - __bfloat162float(hi));
            g_Wpk[off] = hi;
            g_Wpk[off + W1_PL_E] = lo;
        } else {
            int k2 = k - 256;
            const float *w = (g == 0) ? wf2 : (g == 1) ? wi2 : (g == 2) ? wc2 : wo2;
            val = w[k2 * UDIM + u];
            off = (long)nT * WSLICE + W2_BASE_E + n * 520 + k2;
            __nv_bfloat16 hi = __float2bfloat16(val);
            __nv_bfloat16 lo = __float2bfloat16(val - __bfloat162float(hi));
            g_Wpk[off] = hi;
            g_Wpk[off + W2_PL_E] = lo;
        }
    }
    for (long j = i; j < NCOL; j += stride) {
        int g = (int)(j & 3), u = (int)(j >> 2);
        const float *b = (g == 0) ? bf2 : (g == 1) ? bi2 : (g == 2) ? bc2 : bo2;
        g_b2p[j] = b[u];
    }
    if (i == 0) g_cnt = 0u;
}

// ---------------- proj (fp32): proj[v][u*4+g] = emb[v,:] @ W{g}1[x-rows] + b{g}1 ----------------
__global__ __launch_bounds__(256) void proj_kernel(
    const float *__restrict__ emb,
    const float *__restrict__ wf1, const float *__restrict__ wi1,
    const float *__restrict__ wc1, const float *__restrict__ wo1,
    const float *__restrict__ bf1, const float *__restrict__ bi1,
    const float *__restrict__ bc1, const float *__restrict__ bo1)
{
    __shared__ float As[16][68];
    __shared__ float Bs[16][128];
    const int tid = threadIdx.x;
    const int tx = tid & 15, ty = tid >> 4;
    const int bid = blockIdx.x;
    const int mT = bid >> 3, nT = bid & 7;
    const int m0 = mT << 6, n0 = nT << 7;
    const int la_m = tid >> 2, la_k = (tid & 3) << 2;
    const int lb_k = tid >> 4, lb_n = (tid & 15) << 3;

    float acc[4][8];
#pragma unroll
    for (int r = 0; r < 4; ++r)
#pragma unroll
        for (int j = 0; j < 8; ++j) acc[r][j] = 0.0f;

#pragma unroll 1
    for (int kt = 0; kt < 7; ++kt) {
        const int k0 = kt << 4;
        float4 pa = make_float4(0.f, 0.f, 0.f, 0.f);
        {
            int v = m0 + la_m, k = k0 + la_k;
            if (v < VOCAB && k < EDIM)
                pa = *(const float4 *)(emb + (size_t)v * EDIM + k);
        }
        float pb[8];
        {
            int k = k0 + lb_k;
            bool val = (k < EDIM);
            int wrow = (UDIM + k) * UDIM;
            int uc = (n0 + lb_n) >> 2;
            pb[0] = val ? __ldg(&wf1[wrow + uc]) : 0.f;
            pb[1] = val ? __ldg(&wi1[wrow + uc]) : 0.f;
            pb[2] = val ? __ldg(&wc1[wrow + uc]) : 0.f;
            pb[3] = val ? __ldg(&wo1[wrow + uc]) : 0.f;
            pb[4] = val ? __ldg(&wf1[wrow + uc + 1]) : 0.f;
            pb[5] = val ? __ldg(&wi1[wrow + uc + 1]) : 0.f;
            pb[6] = val ? __ldg(&wc1[wrow + uc + 1]) : 0.f;
            pb[7] = val ? __ldg(&wo1[wrow + uc + 1]) : 0.f;
        }
        __syncthreads();
        As[la_k + 0][la_m] = pa.x;
        As[la_k + 1][la_m] = pa.y;
        As[la_k + 2][la_m] = pa.z;
        As[la_k + 3][la_m] = pa.w;
#pragma unroll
        for (int j = 0; j < 8; ++j) Bs[lb_k][lb_n + j] = pb[j];
        __syncthreads();
#pragma unroll
        for (int kk = 0; kk < 16; ++kk) {
            float4 a4 = *(const float4 *)&As[kk][ty << 2];
            float4 b4a = *(const float4 *)&Bs[kk][tx << 3];
            float4 b4b = *(const float4 *)&Bs[kk][(tx << 3) + 4];
            float av[4] = {a4.x, a4.y, a4.z, a4.w};
            float bv[8] = {b4a.x, b4a.y, b4a.z, b4a.w, b4b.x, b4b.y, b4b.z, b4b.w};
#pragma unroll
            for (int r = 0; r < 4; ++r)
#pragma unroll
                for (int j = 0; j < 8; ++j) acc[r][j] = fmaf(av[r], bv[j], acc[r][j]);
        }
    }
#pragma unroll
    for (int r = 0; r < 4; ++r) {
        int v = m0 + (ty << 2) + r;
        if (v < VOCAB) {
            int colb = n0 + (tx << 3);
            int u = colb >> 2;
            float *dst = g_proj + (size_t)v * NCOL + colb;
            dst[0] = acc[r][0] + __ldg(&bf1[u]);
            dst[1] = acc[r][1] + __ldg(&bi1[u]);
            dst[2] = acc[r][2] + __ldg(&bc1[u]);
            dst[3] = acc[r][3] + __ldg(&bo1[u]);
            dst[4] = acc[r][4] + __ldg(&bf1[u + 1]);
            dst[5] = acc[r][5] + __ldg(&bi1[u + 1]);
            dst[6] = acc[r][6] + __ldg(&bc1[u + 1]);
            dst[7] = acc[r][7] + __ldg(&bo1[u + 1]);
        }
    }
}

// one k16 chunk of split-bf16 MMAs
__device__ __forceinline__ void chunk_mma(
    float (&acc)[2][4][4], uint32_t sb, const char *smc,
    const uint32_t (&a_base)[2][2], uint32_t abuf_off,
    const uint32_t (&wb)[2][4], uint32_t koff)
{
    uint32_t ah[2][4], al[2][4];
    ldmatrix4(ah[0], a_base[0][0] + abuf_off);
    ldmatrix4(ah[1], a_base[0][1] + abuf_off);
    ldmatrix4(al[0], a_base[1][0] + abuf_off);
    ldmatrix4(al[1], a_base[1][1] + abuf_off);
    uint32_t bh[4][2], bl[4][2];
#pragma unroll
    for (int fn = 0; fn < 4; ++fn) {
        bh[fn][0] = *(const uint32_t *)(smc + wb[0][fn] + koff);
        bh[fn][1] = *(const uint32_t *)(smc + wb[0][fn] + koff + 16);
        bl[fn][0] = *(const uint32_t *)(smc + wb[1][fn] + koff);
        bl[fn][1] = *(const uint32_t *)(smc + wb[1][fn] + koff + 16);
    }
#pragma unroll
    for (int fn = 0; fn < 4; ++fn) {
        mma_bf16(acc[0][fn], ah[0], bh[fn]);
        mma_bf16(acc[1][fn], ah[1], bh[fn]);
        mma_bf16(acc[0][fn], ah[0], bl[fn]);
        mma_bf16(acc[1][fn], ah[1], bl[fn]);
        mma_bf16(acc[0][fn], al[0], bh[fn]);
        mma_bf16(acc[1][fn], al[1], bh[fn]);
    }
}

// epilogue: combine gate quads via shfl, update c-state, write h hi/lo
template <bool PHASEA>
__device__ __forceinline__ void epilogue(
    float (&acc)[2][4][4], float (&cst)[2][4],
    int t, int m0, int nT, int mw, int nw, int l, int nxt,
    const int *__restrict__ tokens)
{
    const int odd = l & 1;
    const int ul_b = nw * 8 + ((l & 3) >> 1);
#pragma unroll
    for (int fm = 0; fm < 2; ++fm) {
        int row = mw * 32 + fm * 16 + (l >> 2) + (odd ? 8 : 0);
        int b = m0 + row;
        const float *ad4;
        if (PHASEA) {
            int tok = __ldg(&tokens[b * TSTEPS + t]);
            ad4 = g_proj + (size_t)tok * NCOL;
        } else {
            ad4 = g_b2p;
        }
#pragma unroll
        for (int fn = 0; fn < 4; ++fn) {
            float c0 = acc[fm][fn][0], c1 = acc[fm][fn][1];
            float c2 = acc[fm][fn][2], c3 = acc[fm][fn][3];
            float s0 = __shfl_xor_sync(0xffffffffu, c0, 1);
            float s1 = __shfl_xor_sync(0xffffffffu, c1, 1);
            float s2 = __shfl_xor_sync(0xffffffffu, c2, 1);
            float s3 = __shfl_xor_sync(0xffffffffu, c3, 1);
            float gf = odd ? s2 : c0;
            float gi = odd ? s3 : c1;
            float gc = odd ? c2 : s0;
            float go = odd ? c3 : s1;
            int ug = nT * 16 + ul_b + fn * 2;
            float4 ad = *(const float4 *)(ad4 + 4 * ug);
            float pf = gf + ad.x, pi = gi + ad.y, pc = gc + ad.z, po = go + ad.w;
            float cn = sigf(pf) * cst[fm][fn] + sigf(pi) * tanh_(pc);
            cst[fm][fn] = cn;
            float h = sigf(po) * tanh_(cn);
            __nv_bfloat16 hi = __float2bfloat16(h);
            __nv_bfloat16 lo = __float2bfloat16(h - __bfloat162float(hi));
            int col = (PHASEA ? 256 : 0) + ug;
            g_hbf[nxt][0][b][col] = hi;
            g_hbf[nxt][1][b][col] = lo;
            if (!PHASEA && t == TSTEPS - 1) g_h2f[b][ug] = h;
        }
    }
}

// ---------------- persistent recurrent kernel ----------------
__global__ __launch_bounds__(256, 1) void lstm_kernel(
    const int *__restrict__ tokens,
    const float *__restrict__ w_out,
    const float *__restrict__ b_out,
    float *__restrict__ out)
{
    extern __shared__ char smem[];
    const uint32_t sb = smem_u32(smem);
    const int tid = threadIdx.x;
    const int bid = blockIdx.x;
    const int wid = tid >> 5, l = tid & 31;
    const int mT = bid >> 4, nT = bid & 15;
    const int m0 = mT << 7;
    const int mw = wid & 3, nw = wid >> 2;

    // copy resident weight slice (200704 B linear)
    {
        const float4 *src = (const float4 *)(g_Wpk + (size_t)nT * WSLICE);
        float4 *dst = (float4 *)(smem + SM_W1);
        for (int i = tid; i < 12544; i += 256) dst[i] = src[i];
    }

    // constant addresses
    uint32_t a_base[2][2];
#pragma unroll
    for (int pl = 0; pl < 2; ++pl)
#pragma unroll
        for (int fm = 0; fm < 2; ++fm)
            a_base[pl][fm] = sb + SM_A + pl * A_PL +
                             (mw * 32 + fm * 16 + (l & 15)) * A_PITCH + (l >> 4) * 16;
    uint32_t wb1[2][4], wb2[2][4];
#pragma unroll
    for (int pl = 0; pl < 2; ++pl)
#pragma unroll
        for (int fn = 0; fn < 4; ++fn) {
            int n = nw * 32 + fn * 8 + (l >> 2);
            wb1[pl][fn] = SM_W1 + pl * W1_PL + n * W1_PITCH + (l & 3) * 4;
            wb2[pl][fn] = SM_W2 + pl * W2_PL + n * W2_PITCH + (l & 3) * 4;
        }
    const int cp_pl = tid >> 7, cp_row = tid & 127;
    const uint32_t cp_dst0 = sb + SM_A + cp_pl * A_PL + cp_row * A_PITCH;

    float c1st[2][4], c2st[2][4];
#pragma unroll
    for (int a = 0; a < 2; ++a)
#pragma unroll
        for (int b = 0; b < 4; ++b) { c1st[a][b] = 0.f; c2st[a][b] = 0.f; }

    unsigned target = 0;
    __syncthreads();   // weights in smem

#pragma unroll 1
    for (int t = 0; t < TSTEPS; ++t) {
        const int cur = t & 1, nxt = cur ^ 1;

        // ================= PHASE A: layer-1, K=256 over h1_old =================
        {
            float acc[2][4][4];
#pragma unroll
            for (int a = 0; a < 2; ++a)
#pragma unroll
                for (int f = 0; f < 4; ++f)
#pragma unroll
                    for (int j = 0; j < 4; ++j) acc[a][f][j] = 0.f;

            // prefetch chunk 0
            {
                const __nv_bfloat16 *s = &g_hbf[cur][cp_pl][m0 + cp_row][256];
                cpa16(cp_dst0, s);
                cpa16(cp_dst0 + 16, s + 8);
                asm volatile("cp.async.commit_group;" ::: "memory");
            }
#pragma unroll 2
            for (int kc = 0; kc < 16; ++kc) {
                if (kc < 15) {
                    const __nv_bfloat16 *s = &g_hbf[cur][cp_pl][m0 + cp_row][256 + (kc + 1) * 16];
                    uint32_t d = cp_dst0 + ((kc + 1) & 1) * A_BUF;
                    cpa16(d, s);
                    cpa16(d + 16, s + 8);
                    asm volatile("cp.async.commit_group;" ::: "memory");
                    asm volatile("cp.async.wait_group 1;" ::: "memory");
                } else {
                    asm volatile("cp.async.wait_group 0;" ::: "memory");
                }
                __syncthreads();
                chunk_mma(acc, sb, smem, a_base, (kc & 1) * A_BUF, wb1, kc * 32);
                __syncthreads();
            }
            epilogue<true>(acc, c1st, t, m0, nT, mw, nw, l, nxt, tokens);
        }
        gsync(target);

        // ================= PHASE B: layer-2, K=512 over [h2_old | h1_new] =================
        {
            float acc[2][4][4];
#pragma unroll
            for (int a = 0; a < 2; ++a)
#pragma unroll
                for (int f = 0; f < 4; ++f)
#pragma unroll
                    for (int j = 0; j < 4; ++j) acc[a][f][j] = 0.f;

            {
                const __nv_bfloat16 *s = &g_hbf[cur][cp_pl][m0 + cp_row][0];
                cpa16(cp_dst0, s);
                cpa16(cp_dst0 + 16, s + 8);
                asm volatile("cp.async.commit_group;" ::: "memory");
            }
#pragma unroll 2
            for (int kc = 0; kc < 32; ++kc) {
                if (kc < 31) {
                    int kn = kc + 1;
                    int buf = (kn < 16) ? cur : nxt;
                    const __nv_bfloat16 *s = &g_hbf[buf][cp_pl][m0 + cp_row][kn * 16];
                    uint32_t d = cp_dst0 + (kn & 1) * A_BUF;
                    cpa16(d, s);
                    cpa16(d + 16, s + 8);
                    asm volatile("cp.async.commit_group;" ::: "memory");
                    asm volatile("cp.async.wait_group 1;" ::: "memory");
                } else {
                    asm volatile("cp.async.wait_group 0;" ::: "memory");
                }
                __syncthreads();
                chunk_mma(acc, sb, smem, a_base, (kc & 1) * A_BUF, wb2, kc * 32);
                __syncthreads();
            }
            epilogue<false>(acc, c2st, t, m0, nT, mw, nw, l, nxt, tokens);
        }
        gsync(target);
    }

    // ---- output: out[b] = sigmoid(h2[b] . w_out + b_out) ----
    {
        int w = (bid << 3) + wid;
        float s = 0.0f;
#pragma unroll
        for (int k = l; k < UDIM; k += 32)
            s += g_h2f[w][k] * __ldg(&w_out[k]);
#pragma unroll
        for (int off = 16; off > 0; off >>= 1)
            s += __shfl_down_sync(0xffffffffu, s, off);
        if (l == 0) out[w] = sigf(s + __ldg(&b_out[0]));
    }
}

// ---------------- launch ----------------
extern "C" void kernel_launch(void *const *d_in, const int *in_sizes, int n_in,
                              void *d_out, int out_size)
{
    const int   *tokens = (const int *)d_in[0];
    const float *emb = (const float *)d_in[1];
    const float *wf1 = (const float *)d_in[2];
    const float *bf1 = (const float *)d_in[3];
    const float *wi1 = (const float *)d_in[4];
    const float *bi1 = (const float *)d_in[5];
    const float *wc1 = (const float *)d_in[6];
    const float *bc1 = (const float *)d_in[7];
    const float *wo1 = (const float *)d_in[8];
    const float *bo1 = (const float *)d_in[9];
    const float *wf2 = (const float *)d_in[10];
    const float *bf2 = (const float *)d_in[11];
    const float *wi2 = (const float *)d_in[12];
    const float *bi2 = (const float *)d_in[13];
    const float *wc2 = (const float *)d_in[14];
    const float *bc2 = (const float *)d_in[15];
    const float *wo2 = (const float *)d_in[16];
    const float *bo2 = (const float *)d_in[17];
    const float *w_out = (const float *)d_in[18];
    const float *b_out = (const float *)d_in[19];
    float *out = (float *)d_out;

    static int smem_set = 0;
    if (!smem_set) {
        cudaFuncSetAttribute(lstm_kernel, cudaFuncAttributeMaxDynamicSharedMemorySize, SMEM_TOTAL);
        smem_set = 1;
    }

    init_kernel<<<1024, 256>>>(wf1, wi1, wc1, wo1, wf2, wi2, wc2, wo2, bf2, bi2, bc2, bo2);
    proj_kernel<<<1256, 256>>>(emb, wf1, wi1, wc1, wo1, bf1, bi1, bc1, bo1);
    lstm_kernel<<<NBLK, 256, SMEM_TOTAL>>>(tokens, w_out, b_out, out);
}

// round 7
// speedup vs baseline: 3.6546x; 1.9512x over previous
#include <cuda_runtime.h>
#include <cuda_fp16.h>
#include <cstdint>

#define BATCH  1024
#define TSTEPS 80
#define EDIM   100
#define UDIM   256
#define VOCAB  10000
#define NCOL   1024   // 4 gates * U, packed col = u*4+g (g:0=f,1=i,2=c,3=o)
#define NBLK   128

// ---- smem layout (bytes) ----
#define A_PITCH 80
#define A_BUF   10240          // 128 rows * 80
#define SM_A    0              // 2 buffers = 20480
#define SM_W1   20480          // 64 n * 528
#define SM_W2   54272          // 64 n * 1040
#define SMEM_TOTAL 120832

// packed weight slice per nT (fp16 elems)
#define WSLICE   50176         // 64*264 + 64*520
#define W2BASE_E 16896

// ---------------- device scratch ----------------
__device__ float    g_proj[(size_t)VOCAB * NCOL];  // emb@Wx+b1, fp32, gate-interleaved
__device__ __half   g_Wpk[16 * WSLICE];            // packed fp16 weights per nT
__device__ float    g_b2p[NCOL];
__device__ __half   g_hbf[2][BATCH][512];          // [buf][b][col] col: 0-255 h2, 256-511 h1
__device__ float    g_h2f[BATCH][UDIM];
__device__ unsigned g_cntg[8 * 32];                // per-mT-group barrier counters (padded)

// ---------------- helpers ----------------
__device__ __forceinline__ uint32_t smem_u32(const void *p) {
    uint32_t a;
    asm("{ .reg .u64 t; cvta.to.shared.u64 t, %1; cvt.u32.u64 %0, t; }" : "=r"(a) : "l"(p));
    return a;
}
__device__ __forceinline__ void mma_f16(float *c, const uint32_t *a, const uint32_t *b) {
    asm volatile(
        "mma.sync.aligned.m16n8k16.row.col.f32.f16.f16.f32 "
        "{%0,%1,%2,%3}, {%4,%5,%6,%7}, {%8,%9}, {%0,%1,%2,%3};"
        : "+f"(c[0]), "+f"(c[1]), "+f"(c[2]), "+f"(c[3])
        : "r"(a[0]), "r"(a[1]), "r"(a[2]), "r"(a[3]), "r"(b[0]), "r"(b[1]));
}
__device__ __forceinline__ void ldmatrix4(uint32_t *r, uint32_t addr) {
    asm volatile("ldmatrix.sync.aligned.m8n8.x4.shared.b16 {%0,%1,%2,%3}, [%4];"
                 : "=r"(r[0]), "=r"(r[1]), "=r"(r[2]), "=r"(r[3]) : "r"(addr));
}
__device__ __forceinline__ void cpa16(uint32_t dst, const void *src) {
    asm volatile("cp.async.cg.shared.global [%0], [%1], 16;" :: "r"(dst), "l"(src) : "memory");
}
__device__ __forceinline__ void stage(uint32_t dst, const __half *s) {
    cpa16(dst, s);
    cpa16(dst + 16, s + 8);
    asm volatile("cp.async.commit_group;" ::: "memory");
}
__device__ __forceinline__ float sigf(float x) { return 1.0f / (1.0f + __expf(-x)); }
__device__ __forceinline__ float tanh_(float x) {
    x = fminf(fmaxf(x, -20.0f), 20.0f);
    float e = __expf(-2.0f * x);
    return (1.0f - e) / (1.0f + e);
}
// per-mT-group barrier (16 CTAs)
__device__ __forceinline__ void gsync(int grp, unsigned &target) {
    __syncthreads();
    if (threadIdx.x == 0) {
        __threadfence();
        atomicAdd(&g_cntg[grp * 32], 1u);
        target += 16;
        while (*((volatile unsigned *)&g_cntg[grp * 32]) < target) { __nanosleep(32); }
        __threadfence();
    }
    __syncthreads();
}

// ---------------- init: pack fp16 weights, zero state ----------------
__global__ void init_kernel(
    const float *wf1, const float *wi1, const float *wc1, const float *wo1,
    const float *wf2, const float *wi2, const float *wc2, const float *wo2,
    const float *bf2, const float *bi2, const float *bc2, const float *bo2)
{
    long i = (long)blockIdx.x * blockDim.x + threadIdx.x;
    long stride = (long)gridDim.x * blockDim.x;
    // zero h state: 2*1024*512 halves = 524288 u32
    for (long j = i; j < 524288L; j += stride) ((uint32_t *)g_hbf)[j] = 0u;
    for (long j = i; j < 256; j += stride) g_cntg[j] = 0u;
    // pack W^T slices: per nT: [L1 (64 x 264)], [L2 (64 x 520)], fp16
    for (long j = i; j < 16L * 64L * 768L; j += stride) {
        int nT = (int)(j / (64 * 768));
        int rem = (int)(j % (64 * 768));
        int n = rem / 768, k = rem % 768;
        int col = nT * 64 + n;
        int u = col >> 2, g = col & 3;
        if (k < 256) {
            const float *w = (g == 0) ? wf1 : (g == 1) ? wi1 : (g == 2) ? wc1 : wo1;
            g_Wpk[(long)nT * WSLICE + n * 264 + k] = __float2half(w[k * UDIM + u]);
        } else {
            int k2 = k - 256;
            const float *w = (g == 0) ? wf2 : (g == 1) ? wi2 : (g == 2) ? wc2 : wo2;
            g_Wpk[(long)nT * WSLICE + W2BASE_E + n * 520 + k2] = __float2half(w[k2 * UDIM + u]);
        }
    }
    for (long j = i; j < NCOL; j += stride) {
        int g = (int)(j & 3), u = (int)(j >> 2);
        const float *b = (g == 0) ? bf2 : (g == 1) ? bi2 : (g == 2) ? bc2 : bo2;
        g_b2p[j] = b[u];
    }
}

// ---------------- proj (fp32): proj[v][u*4+g] = emb[v,:] @ W{g}1[x-rows] + b{g}1 ----------------
__global__ __launch_bounds__(256) void proj_kernel(
    const float *__restrict__ emb,
    const float *__restrict__ wf1, const float *__restrict__ wi1,
    const float *__restrict__ wc1, const float *__restrict__ wo1,
    const float *__restrict__ bf1, const float *__restrict__ bi1,
    const float *__restrict__ bc1, const float *__restrict__ bo1)
{
    __shared__ float As[16][68];
    __shared__ float Bs[16][128];
    const int tid = threadIdx.x;
    const int tx = tid & 15, ty = tid >> 4;
    const int bid = blockIdx.x;
    const int mT = bid >> 3, nT = bid & 7;
    const int m0 = mT << 6, n0 = nT << 7;
    const int la_m = tid >> 2, la_k = (tid & 3) << 2;
    const int lb_k = tid >> 4, lb_n = (tid & 15) << 3;

    float acc[4][8];
#pragma unroll
    for (int r = 0; r < 4; ++r)
#pragma unroll
        for (int j = 0; j < 8; ++j) acc[r][j] = 0.0f;

#pragma unroll 1
    for (int kt = 0; kt < 7; ++kt) {
        const int k0 = kt << 4;
        float4 pa = make_float4(0.f, 0.f, 0.f, 0.f);
        {
            int v = m0 + la_m, k = k0 + la_k;
            if (v < VOCAB && k < EDIM)
                pa = *(const float4 *)(emb + (size_t)v * EDIM + k);
        }
        float pb[8];
        {
            int k = k0 + lb_k;
            bool val = (k < EDIM);
            int wrow = (UDIM + k) * UDIM;
            int uc = (n0 + lb_n) >> 2;
            pb[0] = val ? __ldg(&wf1[wrow + uc]) : 0.f;
            pb[1] = val ? __ldg(&wi1[wrow + uc]) : 0.f;
            pb[2] = val ? __ldg(&wc1[wrow + uc]) : 0.f;
            pb[3] = val ? __ldg(&wo1[wrow + uc]) : 0.f;
            pb[4] = val ? __ldg(&wf1[wrow + uc + 1]) : 0.f;
            pb[5] = val ? __ldg(&wi1[wrow + uc + 1]) : 0.f;
            pb[6] = val ? __ldg(&wc1[wrow + uc + 1]) : 0.f;
            pb[7] = val ? __ldg(&wo1[wrow + uc + 1]) : 0.f;
        }
        __syncthreads();
        As[la_k + 0][la_m] = pa.x;
        As[la_k + 1][la_m] = pa.y;
        As[la_k + 2][la_m] = pa.z;
        As[la_k + 3][la_m] = pa.w;
#pragma unroll
        for (int j = 0; j < 8; ++j) Bs[lb_k][lb_n + j] = pb[j];
        __syncthreads();
#pragma unroll
        for (int kk = 0; kk < 16; ++kk) {
            float4 a4 = *(const float4 *)&As[kk][ty << 2];
            float4 b4a = *(const float4 *)&Bs[kk][tx << 3];
            float4 b4b = *(const float4 *)&Bs[kk][(tx << 3) + 4];
            float av[4] = {a4.x, a4.y, a4.z, a4.w};
            float bv[8] = {b4a.x, b4a.y, b4a.z, b4a.w, b4b.x, b4b.y, b4b.z, b4b.w};
#pragma unroll
            for (int r = 0; r < 4; ++r)
#pragma unroll
                for (int j = 0; j < 8; ++j) acc[r][j] = fmaf(av[r], bv[j], acc[r][j]);
        }
    }
#pragma unroll
    for (int r = 0; r < 4; ++r) {
        int v = m0 + (ty << 2) + r;
        if (v < VOCAB) {
            int colb = n0 + (tx << 3);
            int u = colb >> 2;
            float *dst = g_proj + (size_t)v * NCOL + colb;
            dst[0] = acc[r][0] + __ldg(&bf1[u]);
            dst[1] = acc[r][1] + __ldg(&bi1[u]);
            dst[2] = acc[r][2] + __ldg(&bc1[u]);
            dst[3] = acc[r][3] + __ldg(&bo1[u]);
            dst[4] = acc[r][4] + __ldg(&bf1[u + 1]);
            dst[5] = acc[r][5] + __ldg(&bi1[u + 1]);
            dst[6] = acc[r][6] + __ldg(&bc1[u + 1]);
            dst[7] = acc[r][7] + __ldg(&bo1[u + 1]);
        }
    }
}

// ---------------- one phase: NCH chunks of BK=32, pair-local pipeline ----------------
template <int NCH>
__device__ __forceinline__ void run_phase(
    const char *smc, const uint32_t (&a_base)[2], const uint32_t (&wb)[4],
    uint32_t cp_dst0, const __half *src0, const __half *src1, int barid,
    float (&acc)[2][4][4])
{
#pragma unroll
    for (int kc = 0; kc < NCH; ++kc) {
        asm volatile("cp.async.wait_group 0;" ::: "memory");
        asm volatile("bar.sync %0, 64;" :: "r"(barid) : "memory");
        if (kc + 1 < NCH) {
            const __half *s = ((kc + 1) < 8 ? src0 : src1) + (kc + 1) * 32;
            stage(cp_dst0 + ((kc + 1) & 1) * A_BUF, s);
        }
        const uint32_t abuf = (kc & 1) * A_BUF;
        const uint32_t koff = kc * 64;
#pragma unroll
        for (int ks = 0; ks < 2; ++ks) {
            uint32_t a0[4], a1[4];
            ldmatrix4(a0, a_base[0] + abuf + ks * 32);
            ldmatrix4(a1, a_base[1] + abuf + ks * 32);
            uint32_t b[4][2];
#pragma unroll
            for (int fn = 0; fn < 4; ++fn) {
                b[fn][0] = *(const uint32_t *)(smc + wb[fn] + koff + ks * 32);
                b[fn][1] = *(const uint32_t *)(smc + wb[fn] + koff + ks * 32 + 16);
            }
#pragma unroll
            for (int fn = 0; fn < 4; ++fn) {
                mma_f16(acc[0][fn], a0, b[fn]);
                mma_f16(acc[1][fn], a1, b[fn]);
            }
        }
    }
}

// epilogue: combine gate quads via shfl, update c-state, write h (fp16)
template <bool PHASEA>
__device__ __forceinline__ void epilogue(
    float (&acc)[2][4][4], float (&cst)[2][4],
    int t, int m0, int nT, int mw, int nw, int l, int nxt,
    const int *__restrict__ tokens)
{
    const int odd = l & 1;
    const int ul_b = nw * 8 + ((l & 3) >> 1);
#pragma unroll
    for (int fm = 0; fm < 2; ++fm) {
        int row = mw * 32 + fm * 16 + (l >> 2) + (odd ? 8 : 0);
        int b = m0 + row;
        const float *ad4;
        if (PHASEA) {
            int tok = __ldg(&tokens[b * TSTEPS + t]);
            ad4 = g_proj + (size_t)tok * NCOL;
        } else {
            ad4 = g_b2p;
        }
#pragma unroll
        for (int fn = 0; fn < 4; ++fn) {
            float c0 = acc[fm][fn][0], c1 = acc[fm][fn][1];
            float c2 = acc[fm][fn][2], c3 = acc[fm][fn][3];
            float s0 = __shfl_xor_sync(0xffffffffu, c0, 1);
            float s1 = __shfl_xor_sync(0xffffffffu, c1, 1);
            float s2 = __shfl_xor_sync(0xffffffffu, c2, 1);
            float s3 = __shfl_xor_sync(0xffffffffu, c3, 1);
            float gf = odd ? s2 : c0;
            float gi = odd ? s3 : c1;
            float gc = odd ? c2 : s0;
            float go = odd ? c3 : s1;
            int ug = nT * 16 + ul_b + fn * 2;
            float4 ad = *(const float4 *)(ad4 + 4 * ug);
            float pf = gf + ad.x, pi = gi + ad.y, pc = gc + ad.z, po = go + ad.w;
            float cn = sigf(pf) * cst[fm][fn] + sigf(pi) * tanh_(pc);
            cst[fm][fn] = cn;
            float h = sigf(po) * tanh_(cn);
            int col = (PHASEA ? 256 : 0) + ug;
            g_hbf[nxt][b][col] = __float2half(h);
            if (!PHASEA && t == TSTEPS - 1) g_h2f[b][ug] = h;
        }
    }
}

// ---------------- persistent recurrent kernel ----------------
__global__ __launch_bounds__(256, 1) void lstm_kernel(
    const int *__restrict__ tokens,
    const float *__restrict__ w_out,
    const float *__restrict__ b_out,
    float *__restrict__ out)
{
    extern __shared__ char smem[];
    const uint32_t sb = smem_u32(smem);
    const int tid = threadIdx.x;
    const int bid = blockIdx.x;
    const int wid = tid >> 5, l = tid & 31;
    const int mT = bid >> 4, nT = bid & 15;
    const int m0 = mT << 7;
    const int mw = wid & 3, nw = wid >> 2;
    const int barid = 1 + mw;

    // preload resident fp16 weight slice (100352 B)
    {
        const float4 *src = (const float4 *)(g_Wpk + (size_t)nT * WSLICE);
        float4 *dst = (float4 *)(smem + SM_W1);
        for (int i = tid; i < 6272; i += 256) dst[i] = src[i];
    }

    // constant addresses
    uint32_t a_base[2];
#pragma unroll
    for (int fm = 0; fm < 2; ++fm)
        a_base[fm] = sb + SM_A + (mw * 32 + fm * 16 + (l & 15)) * A_PITCH + (l >> 4) * 16;
    uint32_t wb1[4], wb2[4];
#pragma unroll
    for (int fn = 0; fn < 4; ++fn) {
        int n = nw * 32 + fn * 8 + (l >> 2);
        wb1[fn] = SM_W1 + n * 528 + (l & 3) * 4;
        wb2[fn] = SM_W2 + n * 1040 + (l & 3) * 4;
    }
    const int cp_row = mw * 32 + nw * 16 + (l >> 1);
    const uint32_t cp_dst0 = sb + SM_A + cp_row * A_PITCH + (l & 1) * 32;
    const int srcoff = (l & 1) * 16;

    float c1st[2][4], c2st[2][4];
#pragma unroll
    for (int a = 0; a < 2; ++a)
#pragma unroll
        for (int b = 0; b < 4; ++b) { c1st[a][b] = 0.f; c2st[a][b] = 0.f; }

    unsigned target = 0;
    __syncthreads();   // weights resident

    // initial prefetch: t=0 phase A chunk0 (h1_old cols 256..287)
    stage(cp_dst0, &g_hbf[0][m0 + cp_row][256 + srcoff]);

#pragma unroll 1
    for (int t = 0; t < TSTEPS; ++t) {
        const int cur = t & 1, nxt = cur ^ 1;
        const __half *hcur = &g_hbf[cur][m0 + cp_row][0];
        const __half *hnxt = &g_hbf[nxt][m0 + cp_row][0];

        // ---- PHASE A: layer-1, K=256 (8 chunks) ----
        {
            float acc[2][4][4];
#pragma unroll
            for (int a = 0; a < 2; ++a)
#pragma unroll
                for (int f = 0; f < 4; ++f)
#pragma unroll
                    for (int j = 0; j < 4; ++j) acc[a][f][j] = 0.f;
            const __half *sA = hcur + 256 + srcoff;
            run_phase<8>(smem, a_base, wb1, cp_dst0, sA, sA, barid, acc);
            // prefetch phase-B chunk0 (h2_old col 0) before barrier
            stage(cp_dst0, hcur + srcoff);
            epilogue<true>(acc, c1st, t, m0, nT, mw, nw, l, nxt, tokens);
        }
        gsync(mT, target);

        // ---- PHASE B: layer-2, K=512 (16 chunks: 8 h2_old + 8 h1_new) ----
        {
            float acc[2][4][4];
#pragma unroll
            for (int a = 0; a < 2; ++a)
#pragma unroll
                for (int f = 0; f < 4; ++f)
#pragma unroll
                    for (int j = 0; j < 4; ++j) acc[a][f][j] = 0.f;
            run_phase<16>(smem, a_base, wb2, cp_dst0, hcur + srcoff, hnxt + srcoff, barid, acc);
            // prefetch next step's phase-A chunk0 before barrier
            if (t < TSTEPS - 1) stage(cp_dst0, hnxt + 256 + srcoff);
            epilogue<false>(acc, c2st, t, m0, nT, mw, nw, l, nxt, tokens);
        }
        gsync(mT, target);
    }

    // ---- output: out[b] = sigmoid(h2[b] . w_out + b_out) ----
    {
        int w = (bid << 3) + wid;
        float s = 0.0f;
#pragma unroll
        for (int k = l; k < UDIM; k += 32)
            s += g_h2f[w][k] * __ldg(&w_out[k]);
#pragma unroll
        for (int off = 16; off > 0; off >>= 1)
            s += __shfl_down_sync(0xffffffffu, s, off);
        if (l == 0) out[w] = sigf(s + __ldg(&b_out[0]));
    }
}

// ---------------- launch ----------------
extern "C" void kernel_launch(void *const *d_in, const int *in_sizes, int n_in,
                              void *d_out, int out_size)
{
    const int   *tokens = (const int *)d_in[0];
    const float *emb = (const float *)d_in[1];
    const float *wf1 = (const float *)d_in[2];
    const float *bf1 = (const float *)d_in[3];
    const float *wi1 = (const float *)d_in[4];
    const float *bi1 = (const float *)d_in[5];
    const float *wc1 = (const float *)d_in[6];
    const float *bc1 = (const float *)d_in[7];
    const float *wo1 = (const float *)d_in[8];
    const float *bo1 = (const float *)d_in[9];
    const float *wf2 = (const float *)d_in[10];
    const float *bf2 = (const float *)d_in[11];
    const float *wi2 = (const float *)d_in[12];
    const float *bi2 = (const float *)d_in[13];
    const float *wc2 = (const float *)d_in[14];
    const float *bc2 = (const float *)d_in[15];
    const float *wo2 = (const float *)d_in[16];
    const float *bo2 = (const float *)d_in[17];
    const float *w_out = (const float *)d_in[18];
    const float *b_out = (const float *)d_in[19];
    float *out = (float *)d_out;

    cudaFuncSetAttribute(lstm_kernel, cudaFuncAttributeMaxDynamicSharedMemorySize, SMEM_TOTAL);

    init_kernel<<<1024, 256>>>(wf1, wi1, wc1, wo1, wf2, wi2, wc2, wo2, bf2, bi2, bc2, bo2);
    proj_kernel<<<1256, 256>>>(emb, wf1, wi1, wc1, wo1, bf1, bi1, bc1, bo1);
    lstm_kernel<<<NBLK, 256, SMEM_TOTAL>>>(tokens, w_out, b_out, out);
}

// round 8
// speedup vs baseline: 5.7909x; 1.5845x over previous
#include <cuda_runtime.h>
#include <cuda_fp16.h>
#include <cstdint>

#define BATCH  1024
#define TSTEPS 80
#define EDIM   100
#define UDIM   256
#define VOCAB  10000
#define NCOL   1024   // 4 gates * U, packed col = u*4+g (g:0=f,1=i,2=c,3=o)
#define NBLK   128

// ---- smem layout (bytes) ----
#define A_PITCH 80
#define A_BUF   10240          // 128 rows * 80
#define SM_A    0              // 3 buffers = 30720
#define SM_W1   30720          // 64 n * 528
#define SM_W2   64512          // 64 n * 1040
#define SMEM_TOTAL 131072

// packed weight slice per nT (fp16 elems)
#define WSLICE   50176         // 64*264 + 64*520
#define W2BASE_E 16896

// ---------------- device scratch ----------------
__device__ float    g_proj[(size_t)VOCAB * NCOL];  // emb@Wx+b1, fp32, gate-interleaved
__device__ __half   g_Wpk[16 * WSLICE];            // packed fp16 weights per nT
__device__ float    g_b2p[NCOL];
__device__ __half   g_hbf[2][BATCH][512];          // [buf][b][col] 0-255 h2, 256-511 h1
__device__ float    g_h2f[BATCH][UDIM];
__device__ unsigned g_cntg[8 * 32];                // per-mT-group barrier counters (padded)

// ---------------- helpers ----------------
__device__ __forceinline__ uint32_t smem_u32(const void *p) {
    uint32_t a;
    asm("{ .reg .u64 t; cvta.to.shared.u64 t, %1; cvt.u32.u64 %0, t; }" : "=r"(a) : "l"(p));
    return a;
}
__device__ __forceinline__ void mma_f16(float *c, const uint32_t *a, const uint32_t *b) {
    asm volatile(
        "mma.sync.aligned.m16n8k16.row.col.f32.f16.f16.f32 "
        "{%0,%1,%2,%3}, {%4,%5,%6,%7}, {%8,%9}, {%0,%1,%2,%3};"
        : "+f"(c[0]), "+f"(c[1]), "+f"(c[2]), "+f"(c[3])
        : "r"(a[0]), "r"(a[1]), "r"(a[2]), "r"(a[3]), "r"(b[0]), "r"(b[1]));
}
__device__ __forceinline__ void ldmatrix4(uint32_t *r, uint32_t addr) {
    asm volatile("ldmatrix.sync.aligned.m8n8.x4.shared.b16 {%0,%1,%2,%3}, [%4];"
                 : "=r"(r[0]), "=r"(r[1]), "=r"(r[2]), "=r"(r[3]) : "r"(addr));
}
__device__ __forceinline__ void cpa16(uint32_t dst, const void *src) {
    asm volatile("cp.async.cg.shared.global [%0], [%1], 16;" :: "r"(dst), "l"(src) : "memory");
}
__device__ __forceinline__ void stage(uint32_t dst, const __half *s) {
    cpa16(dst, s);
    cpa16(dst + 16, s + 8);
    asm volatile("cp.async.commit_group;" ::: "memory");
}
__device__ __forceinline__ float tanhap(float x) {
    float y; asm("tanh.approx.f32 %0, %1;" : "=f"(y) : "f"(x)); return y;
}
__device__ __forceinline__ float sigap(float x) {
    return fmaf(tanhap(0.5f * x), 0.5f, 0.5f);
}
// per-mT-group barrier (16 CTAs): release-red + acquire-ld spin
__device__ __forceinline__ void gsync(int grp, unsigned &target) {
    __syncthreads();
    if (threadIdx.x == 0) {
        unsigned *ctr = &g_cntg[grp * 32];
        asm volatile("red.release.gpu.global.add.u32 [%0], %1;" :: "l"(ctr), "r"(1u) : "memory");
        target += 16;
        unsigned v;
        do {
            asm volatile("ld.acquire.gpu.global.u32 %0, [%1];" : "=r"(v) : "l"(ctr) : "memory");
        } while (v < target);
    }
    __syncthreads();
}

// ---------------- init: pack fp16 weights, zero state ----------------
__global__ void init_kernel(
    const float *wf1, const float *wi1, const float *wc1, const float *wo1,
    const float *wf2, const float *wi2, const float *wc2, const float *wo2,
    const float *bf2, const float *bi2, const float *bc2, const float *bo2)
{
    long i = (long)blockIdx.x * blockDim.x + threadIdx.x;
    long stride = (long)gridDim.x * blockDim.x;
    for (long j = i; j < 524288L; j += stride) ((uint32_t *)g_hbf)[j] = 0u;
    for (long j = i; j < 256; j += stride) g_cntg[j] = 0u;
    for (long j = i; j < 16L * 64L * 768L; j += stride) {
        int nT = (int)(j / (64 * 768));
        int rem = (int)(j % (64 * 768));
        int n = rem / 768, k = rem % 768;
        int col = nT * 64 + n;
        int u = col >> 2, g = col & 3;
        if (k < 256) {
            const float *w = (g == 0) ? wf1 : (g == 1) ? wi1 : (g == 2) ? wc1 : wo1;
            g_Wpk[(long)nT * WSLICE + n * 264 + k] = __float2half(w[k * UDIM + u]);
        } else {
            int k2 = k - 256;
            const float *w = (g == 0) ? wf2 : (g == 1) ? wi2 : (g == 2) ? wc2 : wo2;
            g_Wpk[(long)nT * WSLICE + W2BASE_E + n * 520 + k2] = __float2half(w[k2 * UDIM + u]);
        }
    }
    for (long j = i; j < NCOL; j += stride) {
        int g = (int)(j & 3), u = (int)(j >> 2);
        const float *b = (g == 0) ? bf2 : (g == 1) ? bi2 : (g == 2) ? bc2 : bo2;
        g_b2p[j] = b[u];
    }
}

// ---------------- proj (fp32): proj[v][u*4+g] = emb[v,:] @ W{g}1[x-rows] + b{g}1 ----------------
__global__ __launch_bounds__(256) void proj_kernel(
    const float *__restrict__ emb,
    const float *__restrict__ wf1, const float *__restrict__ wi1,
    const float *__restrict__ wc1, const float *__restrict__ wo1,
    const float *__restrict__ bf1, const float *__restrict__ bi1,
    const float *__restrict__ bc1, const float *__restrict__ bo1)
{
    __shared__ float As[16][68];
    __shared__ float Bs[16][128];
    const int tid = threadIdx.x;
    const int tx = tid & 15, ty = tid >> 4;
    const int bid = blockIdx.x;
    const int mT = bid >> 3, nT = bid & 7;
    const int m0 = mT << 6, n0 = nT << 7;
    const int la_m = tid >> 2, la_k = (tid & 3) << 2;
    const int lb_k = tid >> 4, lb_n = (tid & 15) << 3;

    float acc[4][8];
#pragma unroll
    for (int r = 0; r < 4; ++r)
#pragma unroll
        for (int j = 0; j < 8; ++j) acc[r][j] = 0.0f;

#pragma unroll 1
    for (int kt = 0; kt < 7; ++kt) {
        const int k0 = kt << 4;
        float4 pa = make_float4(0.f, 0.f, 0.f, 0.f);
        {
            int v = m0 + la_m, k = k0 + la_k;
            if (v < VOCAB && k < EDIM)
                pa = *(const float4 *)(emb + (size_t)v * EDIM + k);
        }
        float pb[8];
        {
            int k = k0 + lb_k;
            bool val = (k < EDIM);
            int wrow = (UDIM + k) * UDIM;
            int uc = (n0 + lb_n) >> 2;
            pb[0] = val ? __ldg(&wf1[wrow + uc]) : 0.f;
            pb[1] = val ? __ldg(&wi1[wrow + uc]) : 0.f;
            pb[2] = val ? __ldg(&wc1[wrow + uc]) : 0.f;
            pb[3] = val ? __ldg(&wo1[wrow + uc]) : 0.f;
            pb[4] = val ? __ldg(&wf1[wrow + uc + 1]) : 0.f;
            pb[5] = val ? __ldg(&wi1[wrow + uc + 1]) : 0.f;
            pb[6] = val ? __ldg(&wc1[wrow + uc + 1]) : 0.f;
            pb[7] = val ? __ldg(&wo1[wrow + uc + 1]) : 0.f;
        }
        __syncthreads();
        As[la_k + 0][la_m] = pa.x;
        As[la_k + 1][la_m] = pa.y;
        As[la_k + 2][la_m] = pa.z;
        As[la_k + 3][la_m] = pa.w;
#pragma unroll
        for (int j = 0; j < 8; ++j) Bs[lb_k][lb_n + j] = pb[j];
        __syncthreads();
#pragma unroll
        for (int kk = 0; kk < 16; ++kk) {
            float4 a4 = *(const float4 *)&As[kk][ty << 2];
            float4 b4a = *(const float4 *)&Bs[kk][tx << 3];
            float4 b4b = *(const float4 *)&Bs[kk][(tx << 3) + 4];
            float av[4] = {a4.x, a4.y, a4.z, a4.w};
            float bv[8] = {b4a.x, b4a.y, b4a.z, b4a.w, b4b.x, b4b.y, b4b.z, b4b.w};
#pragma unroll
            for (int r = 0; r < 4; ++r)
#pragma unroll
                for (int j = 0; j < 8; ++j) acc[r][j] = fmaf(av[r], bv[j], acc[r][j]);
        }
    }
#pragma unroll
    for (int r = 0; r < 4; ++r) {
        int v = m0 + (ty << 2) + r;
        if (v < VOCAB) {
            int colb = n0 + (tx << 3);
            int u = colb >> 2;
            float *dst = g_proj + (size_t)v * NCOL + colb;
            dst[0] = acc[r][0] + __ldg(&bf1[u]);
            dst[1] = acc[r][1] + __ldg(&bi1[u]);
            dst[2] = acc[r][2] + __ldg(&bc1[u]);
            dst[3] = acc[r][3] + __ldg(&bo1[u]);
            dst[4] = acc[r][4] + __ldg(&bf1[u + 1]);
            dst[5] = acc[r][5] + __ldg(&bi1[u + 1]);
            dst[6] = acc[r][6] + __ldg(&bc1[u + 1]);
            dst[7] = acc[r][7] + __ldg(&bo1[u + 1]);
        }
    }
}

// chunk source within a step (continuous chunk numbering; 24,25 = next step's A chunks 0,1)
__device__ __forceinline__ const __half *chunk_src(int c, const __half *hcur, const __half *hnxt) {
    if (c < 8)  return hcur + 256 + c * 32;      // phase A: h1_old
    if (c < 16) return hcur + (c - 8) * 32;      // phase B half1: h2_old
    return hnxt + 256 + ((c - 16) & 7) * 32;     // phase B half2 / next A: h1_new
}

// 16 MMAs on one BK=32 chunk
__device__ __forceinline__ void chunk_body(
    const char *smc, const uint32_t (&a_base)[2], const uint32_t (&wb)[4],
    uint32_t abuf, uint32_t koff, float (&acc)[2][4][4])
{
#pragma unroll
    for (int ks = 0; ks < 2; ++ks) {
        uint32_t a0[4], a1[4];
        ldmatrix4(a0, a_base[0] + abuf + ks * 32);
        ldmatrix4(a1, a_base[1] + abuf + ks * 32);
        uint32_t b[4][2];
#pragma unroll
        for (int fn = 0; fn < 4; ++fn) {
            b[fn][0] = *(const uint32_t *)(smc + wb[fn] + koff + ks * 32);
            b[fn][1] = *(const uint32_t *)(smc + wb[fn] + koff + ks * 32 + 16);
        }
#pragma unroll
        for (int fn = 0; fn < 4; ++fn) {
            mma_f16(acc[0][fn], a0, b[fn]);
            mma_f16(acc[1][fn], a1, b[fn]);
        }
    }
}

// epilogue: combine gate quads via shfl, update c-state, write h (fp16)
template <bool PHASEA>
__device__ __forceinline__ void epilogue(
    float (&acc)[2][4][4], float (&cst)[2][4], const float4 (&ad)[2][4],
    const int (&brow)[2], int ug0, int l, int nxt, bool storef)
{
    const int odd = l & 1;
#pragma unroll
    for (int fm = 0; fm < 2; ++fm) {
        int b = brow[fm];
#pragma unroll
        for (int fn = 0; fn < 4; ++fn) {
            float c0 = acc[fm][fn][0], c1 = acc[fm][fn][1];
            float c2 = acc[fm][fn][2], c3 = acc[fm][fn][3];
            float s0 = __shfl_xor_sync(0xffffffffu, c0, 1);
            float s1 = __shfl_xor_sync(0xffffffffu, c1, 1);
            float s2 = __shfl_xor_sync(0xffffffffu, c2, 1);
            float s3 = __shfl_xor_sync(0xffffffffu, c3, 1);
            float gf = odd ? s2 : c0;
            float gi = odd ? s3 : c1;
            float gc = odd ? c2 : s0;
            float go = odd ? c3 : s1;
            float4 a4 = ad[fm][fn];
            float pf = gf + a4.x, pi = gi + a4.y, pc = gc + a4.z, po = go + a4.w;
            float cn = sigap(pf) * cst[fm][fn] + sigap(pi) * tanhap(pc);
            cst[fm][fn] = cn;
            float h = sigap(po) * tanhap(cn);
            int ug = ug0 + fn * 2;
            int col = (PHASEA ? 256 : 0) + ug;
            g_hbf[nxt][b][col] = __float2half(h);
            if (!PHASEA && storef) g_h2f[b][ug] = h;
        }
    }
}

// ---------------- persistent recurrent kernel ----------------
__global__ __launch_bounds__(256, 1) void lstm_kernel(
    const int *__restrict__ tokens,
    const float *__restrict__ w_out,
    const float *__restrict__ b_out,
    float *__restrict__ out)
{
    extern __shared__ char smem[];
    const uint32_t sb = smem_u32(smem);
    const int tid = threadIdx.x;
    const int bid = blockIdx.x;
    const int wid = tid >> 5, l = tid & 31;
    const int mT = bid >> 4, nT = bid & 15;
    const int m0 = mT << 7;
    const int mw = wid & 3, nw = wid >> 2;
    const int barid = 1 + mw;

    // preload resident fp16 weight slice (100352 B)
    {
        const float4 *src = (const float4 *)(g_Wpk + (size_t)nT * WSLICE);
        float4 *dst = (float4 *)(smem + SM_W1);
        for (int i = tid; i < 6272; i += 256) dst[i] = src[i];
    }

    // constant addresses
    uint32_t a_base[2];
#pragma unroll
    for (int fm = 0; fm < 2; ++fm)
        a_base[fm] = sb + SM_A + (mw * 32 + fm * 16 + (l & 15)) * A_PITCH + (l >> 4) * 16;
    uint32_t wb1[4], wb2[4];
#pragma unroll
    for (int fn = 0; fn < 4; ++fn) {
        int n = nw * 32 + fn * 8 + (l >> 2);
        wb1[fn] = SM_W1 + n * 528 + (l & 3) * 4;
        wb2[fn] = SM_W2 + n * 1040 + (l & 3) * 4;
    }
    const int cp_row = mw * 32 + nw * 16 + (l >> 1);
    const uint32_t cp_dst0 = sb + SM_A + cp_row * A_PITCH + (l & 1) * 32;
    const int srcoff = (l & 1) * 16;

    // epilogue row/col constants
    const int odd = l & 1;
    const int ul_b = nw * 8 + ((l & 3) >> 1);
    const int ug0 = nT * 16 + ul_b;
    int brow[2];
#pragma unroll
    for (int fm = 0; fm < 2; ++fm)
        brow[fm] = m0 + mw * 32 + fm * 16 + (l >> 2) + (odd ? 8 : 0);

    // layer-2 bias addends: constant across steps
    float4 adB[2][4];
#pragma unroll
    for (int fn = 0; fn < 4; ++fn) {
        float4 v = *(const float4 *)(g_b2p + 4 * (ug0 + fn * 2));
        adB[0][fn] = v;
        adB[1][fn] = v;
    }

    float c1st[2][4], c2st[2][4];
#pragma unroll
    for (int a = 0; a < 2; ++a)
#pragma unroll
        for (int b = 0; b < 4; ++b) { c1st[a][b] = 0.f; c2st[a][b] = 0.f; }

    unsigned target = 0;
    __syncthreads();   // weights resident

    // prologue: stage chunks 0,1 of t=0 (h1_old)
    {
        const __half *h0 = &g_hbf[0][m0 + cp_row][0];
        stage(cp_dst0, h0 + 256 + srcoff);
        stage(cp_dst0 + A_BUF, h0 + 288 + srcoff);
    }

#pragma unroll 1
    for (int t = 0; t < TSTEPS; ++t) {
        const int cur = t & 1, nxt = cur ^ 1;
        const __half *hcur = &g_hbf[cur][m0 + cp_row][0];
        const __half *hnxt = &g_hbf[nxt][m0 + cp_row][0];
        const bool last = (t == TSTEPS - 1);

        // hoist epilogue-A addends (token-dependent proj gathers)
        float4 adA[2][4];
#pragma unroll
        for (int fm = 0; fm < 2; ++fm) {
            int tok = __ldg(&tokens[brow[fm] * TSTEPS + t]);
            const float4 *p = (const float4 *)(g_proj + (size_t)tok * NCOL) + ug0;
#pragma unroll
            for (int fn = 0; fn < 4; ++fn) adA[fm][fn] = __ldg(p + fn * 2);
        }

        // ---- SEG A: layer-1, chunks 0..7 ----
        float acc1[2][4][4];
#pragma unroll
        for (int a = 0; a < 2; ++a)
#pragma unroll
            for (int f = 0; f < 4; ++f)
#pragma unroll
                for (int j = 0; j < 4; ++j) acc1[a][f][j] = 0.f;
#pragma unroll
        for (int k = 0; k < 8; ++k) {
            asm volatile("cp.async.wait_group 1;" ::: "memory");
            asm volatile("bar.sync %0, 64;" :: "r"(barid) : "memory");
            stage(cp_dst0 + ((k + 2) % 3) * A_BUF, chunk_src(k + 2, hcur, hnxt) + srcoff);
            chunk_body(smem, a_base, wb1, (k % 3) * A_BUF, k * 64, acc1);
        }
        epilogue<true>(acc1, c1st, adA, brow, ug0, l, nxt, false);

        // ---- SEG B1: layer-2 over h2_old, chunks 8..15 ----
        float acc2[2][4][4];
#pragma unroll
        for (int a = 0; a < 2; ++a)
#pragma unroll
            for (int f = 0; f < 4; ++f)
#pragma unroll
                for (int j = 0; j < 4; ++j) acc2[a][f][j] = 0.f;
#pragma unroll
        for (int k = 8; k < 16; ++k) {
            if (k < 15) { asm volatile("cp.async.wait_group 1;" ::: "memory"); }
            else        { asm volatile("cp.async.wait_group 0;" ::: "memory"); }
            asm volatile("bar.sync %0, 64;" :: "r"(barid) : "memory");
            if (k + 2 < 16)
                stage(cp_dst0 + ((k + 2) % 3) * A_BUF, chunk_src(k + 2, hcur, hnxt) + srcoff);
            chunk_body(smem, a_base, wb2, (k % 3) * A_BUF, (k - 8) * 64, acc2);
        }
        gsync(mT, target);

        // ---- SEG B2: layer-2 over h1_new, chunks 16..23 ----
        stage(cp_dst0 + (16 % 3) * A_BUF, chunk_src(16, hcur, hnxt) + srcoff);
        stage(cp_dst0 + (17 % 3) * A_BUF, chunk_src(17, hcur, hnxt) + srcoff);
#pragma unroll
        for (int k = 16; k < 24; ++k) {
            if (k == 23 && last) { asm volatile("cp.async.wait_group 0;" ::: "memory"); }
            else                 { asm volatile("cp.async.wait_group 1;" ::: "memory"); }
            asm volatile("bar.sync %0, 64;" :: "r"(barid) : "memory");
            if (k + 2 < 24 || !last)
                stage(cp_dst0 + ((k + 2) % 3) * A_BUF, chunk_src(k + 2, hcur, hnxt) + srcoff);
            chunk_body(smem, a_base, wb2, (k % 3) * A_BUF, (k - 8) * 64, acc2);
        }
        epilogue<false>(acc2, c2st, adB, brow, ug0, l, nxt, last);
        gsync(mT, target);
    }

    // ---- output: out[b] = sigmoid(h2[b] . w_out + b_out) ----
    {
        int w = (bid << 3) + wid;
        float s = 0.0f;
#pragma unroll
        for (int k = l; k < UDIM; k += 32)
            s += g_h2f[w][k] * __ldg(&w_out[k]);
#pragma unroll
        for (int off = 16; off > 0; off >>= 1)
            s += __shfl_down_sync(0xffffffffu, s, off);
        if (l == 0) out[w] = sigap(s + __ldg(&b_out[0]));
    }
}

// ---------------- launch ----------------
extern "C" void kernel_launch(void *const *d_in, const int *in_sizes, int n_in,
                              void *d_out, int out_size)
{
    const int   *tokens = (const int *)d_in[0];
    const float *emb = (const float *)d_in[1];
    const float *wf1 = (const float *)d_in[2];
    const float *bf1 = (const float *)d_in[3];
    const float *wi1 = (const float *)d_in[4];
    const float *bi1 = (const float *)d_in[5];
    const float *wc1 = (const float *)d_in[6];
    const float *bc1 = (const float *)d_in[7];
    const float *wo1 = (const float *)d_in[8];
    const float *bo1 = (const float *)d_in[9];
    const float *wf2 = (const float *)d_in[10];
    const float *bf2 = (const float *)d_in[11];
    const float *wi2 = (const float *)d_in[12];
    const float *bi2 = (const float *)d_in[13];
    const float *wc2 = (const float *)d_in[14];
    const float *bc2 = (const float *)d_in[15];
    const float *wo2 = (const float *)d_in[16];
    const float *bo2 = (const float *)d_in[17];
    const float *w_out = (const float *)d_in[18];
    const float *b_out = (const float *)d_in[19];
    float *out = (float *)d_out;

    cudaFuncSetAttribute(lstm_kernel, cudaFuncAttributeMaxDynamicSharedMemorySize, SMEM_TOTAL);

    init_kernel<<<1024, 256>>>(wf1, wi1, wc1, wo1, wf2, wi2, wc2, wo2, bf2, bi2, bc2, bo2);
    proj_kernel<<<1256, 256>>>(emb, wf1, wi1, wc1, wo1, bf1, bi1, bc1, bo1);
    lstm_kernel<<<NBLK, 256, SMEM_TOTAL>>>(tokens, w_out, b_out, out);
}